// round 2
// baseline (speedup 1.0000x reference)
#include <cuda_runtime.h>
#include <cstdint>

#define Bb   4
#define Tt   1024
#define EMBD 1024
#define Hh   16
#define HEAD 64
#define BTR  (Bb * Tt)          // 4096 rows
#define NEG_BIG (-1e30f)

// Scratch (static device allocations are allowed; cudaMalloc is not)
static __device__ float g_Q[(size_t)BTR * EMBD];
static __device__ float g_K[(size_t)BTR * EMBD];
static __device__ float g_V[(size_t)BTR * EMBD];
static __device__ float g_O[(size_t)BTR * EMBD];
static __device__ float g_W[(size_t)Bb * Hh * Tt * Tt];   // 256 MB fallback for attention weights

// ---------------------------------------------------------------------------
// Shared GEMM core: C_tile(BM x BN) accumulate over K.
//   A is [M x K] row-major (k-contiguous), lda given.
//   NT=true : B is [N x K] row-major (k-contiguous)  -> C = A * B^T
//   NT=false: B is [K x N] row-major (n-contiguous)  -> C = A * B
// 256 threads, TM x TN per-thread micro-tile. BK/4 and TN,TM multiples of 4.
// ---------------------------------------------------------------------------
template <int BM, int BN, int BK, int TM, int TN, bool NT>
__device__ __forceinline__ void gemm_core(
    const float* __restrict__ A, int lda,
    const float* __restrict__ B, int ldb,
    int K, int m0, int n0, float (&acc)[TM][TN])
{
    __shared__ float As[BK][BM];
    __shared__ float Bs[BK][BN];
    const int tid = threadIdx.x;
    const int tx  = tid % (BN / TN);
    const int ty  = tid / (BN / TN);

    for (int k0 = 0; k0 < K; k0 += BK) {
        // Load A tile: BM rows x BK cols (k-contiguous) -> transposed into As[k][m]
        #pragma unroll
        for (int i = tid; i < BM * (BK / 4); i += 256) {
            int r = i / (BK / 4);
            int c = (i % (BK / 4)) * 4;
            float4 v = *(const float4*)&A[(size_t)(m0 + r) * lda + k0 + c];
            As[c + 0][r] = v.x; As[c + 1][r] = v.y;
            As[c + 2][r] = v.z; As[c + 3][r] = v.w;
        }
        if (NT) {
            #pragma unroll
            for (int i = tid; i < BN * (BK / 4); i += 256) {
                int r = i / (BK / 4);
                int c = (i % (BK / 4)) * 4;
                float4 v = *(const float4*)&B[(size_t)(n0 + r) * ldb + k0 + c];
                Bs[c + 0][r] = v.x; Bs[c + 1][r] = v.y;
                Bs[c + 2][r] = v.z; Bs[c + 3][r] = v.w;
            }
        } else {
            #pragma unroll
            for (int i = tid; i < BK * (BN / 4); i += 256) {
                int c = i / (BN / 4);
                int r = (i % (BN / 4)) * 4;
                *(float4*)&Bs[c][r] =
                    *(const float4*)&B[(size_t)(k0 + c) * ldb + n0 + r];
            }
        }
        __syncthreads();

        #pragma unroll
        for (int kk = 0; kk < BK; kk++) {
            float ra[TM], rb[TN];
            #pragma unroll
            for (int i = 0; i < TM; i += 4)
                *(float4*)&ra[i] = *(const float4*)&As[kk][ty * TM + i];
            #pragma unroll
            for (int j = 0; j < TN; j += 4)
                *(float4*)&rb[j] = *(const float4*)&Bs[kk][tx * TN + j];
            #pragma unroll
            for (int i = 0; i < TM; i++)
                #pragma unroll
                for (int j = 0; j < TN; j++)
                    acc[i][j] += ra[i] * rb[j];
        }
        __syncthreads();
    }
}

// ---------------------------------------------------------------------------
// Projection / output GEMM: C[M,N] = alpha * A[M,K] * B[N,K]^T
// ---------------------------------------------------------------------------
template <int BM, int BN, int BK, int TM, int TN>
__global__ void __launch_bounds__(256)
gemm_nt_kernel(const float* __restrict__ A, int lda,
               const float* __restrict__ B, int ldb,
               float* __restrict__ C, int ldc,
               int K, float alpha)
{
    float acc[TM][TN] = {};
    const int m0 = blockIdx.y * BM;
    const int n0 = blockIdx.x * BN;
    gemm_core<BM, BN, BK, TM, TN, true>(A, lda, B, ldb, K, m0, n0, acc);

    const int tx = threadIdx.x % (BN / TN);
    const int ty = threadIdx.x / (BN / TN);
    #pragma unroll
    for (int i = 0; i < TM; i++) {
        size_t row = (size_t)(m0 + ty * TM + i) * ldc + n0 + tx * TN;
        #pragma unroll
        for (int j = 0; j < TN; j += 4) {
            float4 v = make_float4(acc[i][j + 0] * alpha, acc[i][j + 1] * alpha,
                                   acc[i][j + 2] * alpha, acc[i][j + 3] * alpha);
            *(float4*)&C[row + j] = v;
        }
    }
}

// ---------------------------------------------------------------------------
// Scores: W[z, t, s] = mask ? -1e30 : (Q[b,:,h,:] K[b,:,h,:]^T)[t,s] * 1/sqrt(HEAD)
// z = b*H + h. Batched NT GEMM with K-dim = HEAD = 64.
// Mask is read as 4-byte words (covers both int32 and float32 encodings of
// the original bool array): nonzero word == masked.
// ---------------------------------------------------------------------------
__global__ void __launch_bounds__(256)
scores_kernel(const float* __restrict__ Q, const float* __restrict__ Kc,
              const int* __restrict__ mask, float* __restrict__ Wt)
{
    const int z = blockIdx.z;
    const int b = z >> 4;
    const int h = z & 15;
    const float* A  = Q  + (size_t)b * Tt * EMBD + h * HEAD;
    const float* Bp = Kc + (size_t)b * Tt * EMBD + h * HEAD;

    float acc[8][8] = {};
    const int m0 = blockIdx.y * 128;
    const int n0 = blockIdx.x * 128;
    gemm_core<128, 128, 8, 8, 8, true>(A, EMBD, Bp, EMBD, HEAD, m0, n0, acc);

    float* C = Wt + (size_t)z * Tt * Tt;
    const int* mrow = mask + (size_t)b * Tt * Tt;
    const int tx = threadIdx.x % 16;
    const int ty = threadIdx.x / 16;
    const float scale = 0.125f;  // 1/sqrt(64)
    #pragma unroll
    for (int i = 0; i < 8; i++) {
        int t = m0 + ty * 8 + i;
        #pragma unroll
        for (int j = 0; j < 8; j++) {
            int s = n0 + tx * 8 + j;
            float v = (mrow[(size_t)t * Tt + s] != 0) ? NEG_BIG : acc[i][j] * scale;
            C[(size_t)t * Tt + s] = v;
        }
    }
}

// ---------------------------------------------------------------------------
// Row softmax over 1024 elements, fully-masked rows -> all zeros.
// One block (256 threads) per row; each thread owns one float4.
// ---------------------------------------------------------------------------
__global__ void __launch_bounds__(256)
softmax_kernel(float* __restrict__ Wt)
{
    __shared__ float red[8];
    float4* w = reinterpret_cast<float4*>(Wt + (size_t)blockIdx.x * Tt);
    const int t = threadIdx.x;
    float4 v = w[t];

    float m = fmaxf(fmaxf(v.x, v.y), fmaxf(v.z, v.w));
    #pragma unroll
    for (int o = 16; o > 0; o >>= 1) m = fmaxf(m, __shfl_xor_sync(0xffffffffu, m, o));
    if ((t & 31) == 0) red[t >> 5] = m;
    __syncthreads();
    float rm = red[0];
    #pragma unroll
    for (int i = 1; i < 8; i++) rm = fmaxf(rm, red[i]);

    const bool dead = (rm <= -1e29f);   // fully-masked row
    float e0 = dead ? 0.f : __expf(v.x - rm);
    float e1 = dead ? 0.f : __expf(v.y - rm);
    float e2 = dead ? 0.f : __expf(v.z - rm);
    float e3 = dead ? 0.f : __expf(v.w - rm);
    float s = e0 + e1 + e2 + e3;
    #pragma unroll
    for (int o = 16; o > 0; o >>= 1) s += __shfl_xor_sync(0xffffffffu, s, o);
    __syncthreads();
    if ((t & 31) == 0) red[t >> 5] = s;
    __syncthreads();
    float tot = 0.f;
    #pragma unroll
    for (int i = 0; i < 8; i++) tot += red[i];
    float inv = (tot > 0.f) ? (1.f / tot) : 0.f;

    w[t] = make_float4(e0 * inv, e1 * inv, e2 * inv, e3 * inv);
}

// ---------------------------------------------------------------------------
// AV: O[b, t, h*64 + d] = sum_s W[z, t, s] * V[b, s, h*64 + d]   (NN GEMM)
// ---------------------------------------------------------------------------
__global__ void __launch_bounds__(256)
av_kernel(const float* __restrict__ Wt, const float* __restrict__ V,
          float* __restrict__ O)
{
    const int z = blockIdx.z;
    const int b = z >> 4;
    const int h = z & 15;
    const float* A  = Wt + (size_t)z * Tt * Tt;
    const float* Bp = V + (size_t)b * Tt * EMBD + h * HEAD;

    float acc[8][4] = {};
    const int m0 = blockIdx.y * 128;
    gemm_core<128, 64, 8, 8, 4, false>(A, Tt, Bp, EMBD, Tt, m0, 0, acc);

    float* C = O + (size_t)b * Tt * EMBD + h * HEAD;
    const int tx = threadIdx.x % 16;
    const int ty = threadIdx.x / 16;
    #pragma unroll
    for (int i = 0; i < 8; i++) {
        size_t row = (size_t)(m0 + ty * 8 + i) * EMBD + tx * 4;
        *(float4*)&C[row] = make_float4(acc[i][0], acc[i][1], acc[i][2], acc[i][3]);
    }
}

// ---------------------------------------------------------------------------
extern "C" void kernel_launch(void* const* d_in, const int* in_sizes, int n_in,
                              void* d_out, int out_size)
{
    const float* x    = (const float*)d_in[0];
    const float* ctx  = (const float*)d_in[1];
    const int*   mask = (const int*)d_in[2];   // bool widened to 4-byte (int32 or f32)
    const float* WQ = (const float*)d_in[3];
    const float* WK = (const float*)d_in[4];
    const float* WV = (const float*)d_in[5];
    const float* WO = (const float*)d_in[6];
    float* out = (float*)d_out;

    float *qp, *kp, *vp, *op;
    cudaGetSymbolAddress((void**)&qp, g_Q);
    cudaGetSymbolAddress((void**)&kp, g_K);
    cudaGetSymbolAddress((void**)&vp, g_V);
    cudaGetSymbolAddress((void**)&op, g_O);

    const size_t merged_elems = (size_t)BTR * EMBD;                 // 4,194,304
    const size_t weight_elems = (size_t)Bb * Hh * Tt * Tt;         // 67,108,864
    float* wt;
    if ((size_t)out_size >= merged_elems + weight_elems) {
        wt = out + merged_elems;            // weights are part of the output tuple
    } else {
        cudaGetSymbolAddress((void**)&wt, g_W);
    }

    dim3 blk(256);
    dim3 gproj(EMBD / 128, BTR / 128);      // (8, 32)

    // Q/K/V projections: y = x @ W^T
    gemm_nt_kernel<128, 128, 8, 8, 8><<<gproj, blk>>>(x,   EMBD, WQ, EMBD, qp, EMBD, EMBD, 1.f);
    gemm_nt_kernel<128, 128, 8, 8, 8><<<gproj, blk>>>(ctx, EMBD, WK, EMBD, kp, EMBD, EMBD, 1.f);
    gemm_nt_kernel<128, 128, 8, 8, 8><<<gproj, blk>>>(ctx, EMBD, WV, EMBD, vp, EMBD, EMBD, 1.f);

    // Scores + mask
    dim3 gsc(Tt / 128, Tt / 128, Bb * Hh);  // (8, 8, 64)
    scores_kernel<<<gsc, blk>>>(qp, kp, mask, wt);

    // Row softmax (nan_to_num semantics for fully-masked rows)
    softmax_kernel<<<Bb * Hh * Tt, 256>>>(wt);

    // AV, written directly in merged [B, T, EMB] layout
    dim3 gav(1, Tt / 128, Bb * Hh);         // (1, 8, 64)
    av_kernel<<<gav, blk>>>(wt, vp, op);

    // Output projection into d_out
    gemm_nt_kernel<128, 128, 8, 8, 8><<<gproj, blk>>>(op, EMBD, WO, EMBD, out, EMBD, EMBD, 1.f);
}

// round 4
// speedup vs baseline: 2.2742x; 2.2742x over previous
#include <cuda_runtime.h>
#include <cuda_bf16.h>
#include <cstdint>

#define Bb   4
#define Tt   1024
#define EMBD 1024
#define Hh   16
#define HEAD 64
#define BTR  (Bb * Tt)
#define NEG_BIG (-1e30f)

static __device__ float g_Q[(size_t)BTR * EMBD];
static __device__ float g_K[(size_t)BTR * EMBD];
static __device__ float g_V[(size_t)BTR * EMBD];
static __device__ float g_O[(size_t)BTR * EMBD];
static __device__ float g_W[(size_t)Bb * Hh * Tt * Tt];

// ===========================================================================
// Warp-MMA helpers (sm_80+ baseline: legal on target sm_103)
// ===========================================================================
__device__ __forceinline__ uint32_t smem_u32(const void* p) {
    uint32_t a;
    asm("{ .reg .u64 t; cvta.to.shared.u64 t, %1; cvt.u32.u64 %0, t; }" : "=r"(a) : "l"(p));
    return a;
}
__device__ __forceinline__ void ldsm4(uint32_t addr, uint32_t& r0, uint32_t& r1,
                                      uint32_t& r2, uint32_t& r3) {
    asm volatile("ldmatrix.sync.aligned.m8n8.x4.shared.b16 {%0,%1,%2,%3}, [%4];"
                 : "=r"(r0), "=r"(r1), "=r"(r2), "=r"(r3) : "r"(addr));
}
__device__ __forceinline__ void ldsm4t(uint32_t addr, uint32_t& r0, uint32_t& r1,
                                       uint32_t& r2, uint32_t& r3) {
    asm volatile("ldmatrix.sync.aligned.m8n8.x4.trans.shared.b16 {%0,%1,%2,%3}, [%4];"
                 : "=r"(r0), "=r"(r1), "=r"(r2), "=r"(r3) : "r"(addr));
}
__device__ __forceinline__ void mma_bf16(float (&d)[4], const uint32_t (&a)[4],
                                         uint32_t b0, uint32_t b1) {
    asm volatile("mma.sync.aligned.m16n8k16.row.col.f32.bf16.bf16.f32 "
                 "{%0,%1,%2,%3},{%4,%5,%6,%7},{%8,%9},{%0,%1,%2,%3};"
                 : "+f"(d[0]), "+f"(d[1]), "+f"(d[2]), "+f"(d[3])
                 : "r"(a[0]), "r"(a[1]), "r"(a[2]), "r"(a[3]), "r"(b0), "r"(b1));
}

// fp32 -> bf16 hi + bf16 residual(lo); 4 elems -> two uint2 (4 bf16 each)
__device__ __forceinline__ void cvt_hilo(float4 v, uint2& hi, uint2& lo) {
    __nv_bfloat162 h0 = __floats2bfloat162_rn(v.x, v.y);
    __nv_bfloat162 h1 = __floats2bfloat162_rn(v.z, v.w);
    float rx = v.x - __bfloat162float(h0.x);
    float ry = v.y - __bfloat162float(h0.y);
    float rz = v.z - __bfloat162float(h1.x);
    float rw = v.w - __bfloat162float(h1.y);
    __nv_bfloat162 l0 = __floats2bfloat162_rn(rx, ry);
    __nv_bfloat162 l1 = __floats2bfloat162_rn(rz, rw);
    hi = make_uint2(*(uint32_t*)&h0, *(uint32_t*)&h1);
    lo = make_uint2(*(uint32_t*)&l0, *(uint32_t*)&l1);
}

// ===========================================================================
// NT GEMM (C = A * B^T), 128x128 block tile, BK=32, 8 warps (2M x 4N),
// warp tile 64x32, bf16 hi/lo 3-pass. SCORES: batched per head + fused
// mask / scale epilogue.
// Smem per stage: A hi/lo + B hi/lo, each 128 rows x 40 elems (pad) bf16.
// ===========================================================================
#define STR_K  40            // padded row stride (elems) for 32-wide k tiles
#define A_HI_O 0
#define A_LO_O 10240
#define B_HI_O 20480
#define B_LO_O 30720
#define STAGE_NT 40960       // bytes per stage

template <bool SCORES>
__global__ void __launch_bounds__(256)
mma_nt(const float* __restrict__ A, const float* __restrict__ Bm,
       const int* __restrict__ mask, float* __restrict__ C, int Kdim)
{
    extern __shared__ __align__(16) char sm[];
    const int tid = threadIdx.x, lane = tid & 31, wid = tid >> 5;

    const float* Ab; const float* Bp; float* Cb; const int* mb = nullptr;
    int lda, ldb, ldc;
    if (SCORES) {
        int z = blockIdx.z, b = z >> 4, h = z & 15;
        Ab = A  + (size_t)b * Tt * EMBD + h * HEAD;
        Bp = Bm + (size_t)b * Tt * EMBD + h * HEAD;
        Cb = C  + (size_t)z * Tt * Tt;
        mb = mask + (size_t)b * Tt * Tt;
        lda = EMBD; ldb = EMBD; ldc = Tt;
    } else {
        Ab = A; Bp = Bm; Cb = C;
        lda = EMBD; ldb = EMBD; ldc = EMBD;
    }
    const int m0 = blockIdx.y * 128;
    const int n0 = blockIdx.x * 128;
    const int NC = Kdim / 32;

    float acc[4][4][4] = {};
    float4 la[4], lb[4];

    // prologue: load + store chunk 0
    {
        #pragma unroll
        for (int i = 0; i < 4; i++) {
            int seg = tid + i * 256, row = seg >> 3, c4 = (seg & 7) << 2;
            la[i] = *(const float4*)&Ab[(size_t)(m0 + row) * lda + c4];
            lb[i] = *(const float4*)&Bp[(size_t)(n0 + row) * ldb + c4];
        }
        #pragma unroll
        for (int i = 0; i < 4; i++) {
            int seg = tid + i * 256, row = seg >> 3, c4 = (seg & 7) << 2;
            uint2 h, l;
            cvt_hilo(la[i], h, l);
            *(uint2*)(sm + A_HI_O + (row * STR_K + c4) * 2) = h;
            *(uint2*)(sm + A_LO_O + (row * STR_K + c4) * 2) = l;
            cvt_hilo(lb[i], h, l);
            *(uint2*)(sm + B_HI_O + (row * STR_K + c4) * 2) = h;
            *(uint2*)(sm + B_LO_O + (row * STR_K + c4) * 2) = l;
        }
    }
    __syncthreads();

    const int wm = wid >> 2, wn = wid & 3;
    const int arow = lane & 15, acol8 = (lane >> 4) << 3;
    const int brow = (lane & 7) + ((lane >> 4) << 3), bcol8 = ((lane >> 3) & 1) << 3;
    const uint32_t sb0 = smem_u32(sm);

    for (int c = 0; c < NC; c++) {
        if (c + 1 < NC) {
            int k0n = (c + 1) * 32;
            #pragma unroll
            for (int i = 0; i < 4; i++) {
                int seg = tid + i * 256, row = seg >> 3, c4 = (seg & 7) << 2;
                la[i] = *(const float4*)&Ab[(size_t)(m0 + row) * lda + k0n + c4];
                lb[i] = *(const float4*)&Bp[(size_t)(n0 + row) * ldb + k0n + c4];
            }
        }
        // compute on stage c&1
        const uint32_t sbase = sb0 + (c & 1) * STAGE_NT;
        #pragma unroll
        for (int ks = 0; ks < 2; ks++) {
            const int k0 = ks * 16;
            uint32_t ah[4][4], al[4][4];
            #pragma unroll
            for (int mt = 0; mt < 4; mt++) {
                int r = wm * 64 + mt * 16 + arow;
                uint32_t ad = sbase + A_HI_O + (r * STR_K + k0 + acol8) * 2;
                ldsm4(ad, ah[mt][0], ah[mt][1], ah[mt][2], ah[mt][3]);
                ldsm4(ad + (A_LO_O - A_HI_O), al[mt][0], al[mt][1], al[mt][2], al[mt][3]);
            }
            uint32_t bh[4][2], bl[4][2];
            #pragma unroll
            for (int bt = 0; bt < 2; bt++) {
                int r = wn * 32 + bt * 16 + brow;
                uint32_t bd = sbase + B_HI_O + (r * STR_K + k0 + bcol8) * 2;
                ldsm4(bd, bh[2 * bt][0], bh[2 * bt][1], bh[2 * bt + 1][0], bh[2 * bt + 1][1]);
                ldsm4(bd + (B_LO_O - B_HI_O),
                      bl[2 * bt][0], bl[2 * bt][1], bl[2 * bt + 1][0], bl[2 * bt + 1][1]);
            }
            #pragma unroll
            for (int mt = 0; mt < 4; mt++)
                #pragma unroll
                for (int nt = 0; nt < 4; nt++) {
                    mma_bf16(acc[mt][nt], ah[mt], bh[nt][0], bh[nt][1]);
                    mma_bf16(acc[mt][nt], ah[mt], bl[nt][0], bl[nt][1]);
                    mma_bf16(acc[mt][nt], al[mt], bh[nt][0], bh[nt][1]);
                }
        }
        if (c + 1 < NC) {
            char* dst = sm + ((c + 1) & 1) * STAGE_NT;
            #pragma unroll
            for (int i = 0; i < 4; i++) {
                int seg = tid + i * 256, row = seg >> 3, c4 = (seg & 7) << 2;
                uint2 h, l;
                cvt_hilo(la[i], h, l);
                *(uint2*)(dst + A_HI_O + (row * STR_K + c4) * 2) = h;
                *(uint2*)(dst + A_LO_O + (row * STR_K + c4) * 2) = l;
                cvt_hilo(lb[i], h, l);
                *(uint2*)(dst + B_HI_O + (row * STR_K + c4) * 2) = h;
                *(uint2*)(dst + B_LO_O + (row * STR_K + c4) * 2) = l;
            }
        }
        __syncthreads();
    }

    // epilogue
    const int rofs = lane >> 2, cofs = (lane & 3) * 2;
    #pragma unroll
    for (int mt = 0; mt < 4; mt++) {
        #pragma unroll
        for (int nt = 0; nt < 4; nt++) {
            int m = m0 + wm * 64 + mt * 16 + rofs;
            int n = n0 + wn * 32 + nt * 8 + cofs;
            if (SCORES) {
                int2 mk0 = *(const int2*)&mb[(size_t)m * Tt + n];
                int2 mk1 = *(const int2*)&mb[(size_t)(m + 8) * Tt + n];
                float2 v0, v1;
                v0.x = mk0.x ? NEG_BIG : acc[mt][nt][0] * 0.125f;
                v0.y = mk0.y ? NEG_BIG : acc[mt][nt][1] * 0.125f;
                v1.x = mk1.x ? NEG_BIG : acc[mt][nt][2] * 0.125f;
                v1.y = mk1.y ? NEG_BIG : acc[mt][nt][3] * 0.125f;
                *(float2*)&Cb[(size_t)m * ldc + n] = v0;
                *(float2*)&Cb[(size_t)(m + 8) * ldc + n] = v1;
            } else {
                *(float2*)&Cb[(size_t)m * ldc + n] =
                    make_float2(acc[mt][nt][0], acc[mt][nt][1]);
                *(float2*)&Cb[(size_t)(m + 8) * ldc + n] =
                    make_float2(acc[mt][nt][2], acc[mt][nt][3]);
            }
        }
    }
}

// ===========================================================================
// AV (NN): O[b, t, h*64+n] = sum_s W[z,t,s] * V[b,s,h*64+n]
// Block 128x64, BK=32, 8 warps (4M x 2N), warp tile 32x32.
// A (weights) k-contiguous -> same path as NT A. B (V) n-contiguous ->
// ldmatrix.trans on [BK][64] tile (stride 72).
// ===========================================================================
#define STR_V   72
#define AV_AHI  0
#define AV_ALO  10240
#define AV_BHI  20480
#define AV_BLO  25088
#define STAGE_AV 29696

__global__ void __launch_bounds__(256)
mma_av(const float* __restrict__ Wt, const float* __restrict__ V,
       float* __restrict__ O)
{
    extern __shared__ __align__(16) char sm[];
    const int tid = threadIdx.x, lane = tid & 31, wid = tid >> 5;
    const int z = blockIdx.z, b = z >> 4, h = z & 15;
    const float* Ab = Wt + (size_t)z * Tt * Tt;
    const float* Vb = V + (size_t)b * Tt * EMBD + h * HEAD;
    const int m0 = blockIdx.y * 128;
    const int NC = Tt / 32;

    float acc[2][4][4] = {};
    float4 la[4]; float4 lv[2];

    {
        #pragma unroll
        for (int i = 0; i < 4; i++) {
            int seg = tid + i * 256, row = seg >> 3, c4 = (seg & 7) << 2;
            la[i] = *(const float4*)&Ab[(size_t)(m0 + row) * Tt + c4];
        }
        #pragma unroll
        for (int i = 0; i < 2; i++) {
            int seg = tid + i * 256, row = seg >> 4, c4 = (seg & 15) << 2;
            lv[i] = *(const float4*)&Vb[(size_t)row * EMBD + c4];
        }
        #pragma unroll
        for (int i = 0; i < 4; i++) {
            int seg = tid + i * 256, row = seg >> 3, c4 = (seg & 7) << 2;
            uint2 hh, ll;
            cvt_hilo(la[i], hh, ll);
            *(uint2*)(sm + AV_AHI + (row * STR_K + c4) * 2) = hh;
            *(uint2*)(sm + AV_ALO + (row * STR_K + c4) * 2) = ll;
        }
        #pragma unroll
        for (int i = 0; i < 2; i++) {
            int seg = tid + i * 256, row = seg >> 4, c4 = (seg & 15) << 2;
            uint2 hh, ll;
            cvt_hilo(lv[i], hh, ll);
            *(uint2*)(sm + AV_BHI + (row * STR_V + c4) * 2) = hh;
            *(uint2*)(sm + AV_BLO + (row * STR_V + c4) * 2) = ll;
        }
    }
    __syncthreads();

    const int wm = wid >> 1, wn = wid & 1;
    const int arow = lane & 15, acol8 = (lane >> 4) << 3;
    const int tbrow = (lane & 7) + ((lane >> 3) & 1) * 8, tbcol8 = (lane >> 4) << 3;
    const uint32_t sb0 = smem_u32(sm);

    for (int c = 0; c < NC; c++) {
        if (c + 1 < NC) {
            int k0n = (c + 1) * 32;
            #pragma unroll
            for (int i = 0; i < 4; i++) {
                int seg = tid + i * 256, row = seg >> 3, c4 = (seg & 7) << 2;
                la[i] = *(const float4*)&Ab[(size_t)(m0 + row) * Tt + k0n + c4];
            }
            #pragma unroll
            for (int i = 0; i < 2; i++) {
                int seg = tid + i * 256, row = seg >> 4, c4 = (seg & 15) << 2;
                lv[i] = *(const float4*)&Vb[(size_t)(k0n + row) * EMBD + c4];
            }
        }
        const uint32_t sbase = sb0 + (c & 1) * STAGE_AV;
        #pragma unroll
        for (int ks = 0; ks < 2; ks++) {
            const int k0 = ks * 16;
            uint32_t ah[2][4], al[2][4];
            #pragma unroll
            for (int mt = 0; mt < 2; mt++) {
                int r = wm * 32 + mt * 16 + arow;
                uint32_t ad = sbase + AV_AHI + (r * STR_K + k0 + acol8) * 2;
                ldsm4(ad, ah[mt][0], ah[mt][1], ah[mt][2], ah[mt][3]);
                ldsm4(ad + (AV_ALO - AV_AHI), al[mt][0], al[mt][1], al[mt][2], al[mt][3]);
            }
            uint32_t bh[4][2], bl[4][2];
            #pragma unroll
            for (int bt = 0; bt < 2; bt++) {
                int col = wn * 32 + bt * 16 + tbcol8;
                uint32_t bd = sbase + AV_BHI + ((k0 + tbrow) * STR_V + col) * 2;
                ldsm4t(bd, bh[2 * bt][0], bh[2 * bt][1], bh[2 * bt + 1][0], bh[2 * bt + 1][1]);
                ldsm4t(bd + (AV_BLO - AV_BHI),
                       bl[2 * bt][0], bl[2 * bt][1], bl[2 * bt + 1][0], bl[2 * bt + 1][1]);
            }
            #pragma unroll
            for (int mt = 0; mt < 2; mt++)
                #pragma unroll
                for (int nt = 0; nt < 4; nt++) {
                    mma_bf16(acc[mt][nt], ah[mt], bh[nt][0], bh[nt][1]);
                    mma_bf16(acc[mt][nt], ah[mt], bl[nt][0], bl[nt][1]);
                    mma_bf16(acc[mt][nt], al[mt], bh[nt][0], bh[nt][1]);
                }
        }
        if (c + 1 < NC) {
            char* dst = sm + ((c + 1) & 1) * STAGE_AV;
            #pragma unroll
            for (int i = 0; i < 4; i++) {
                int seg = tid + i * 256, row = seg >> 3, c4 = (seg & 7) << 2;
                uint2 hh, ll;
                cvt_hilo(la[i], hh, ll);
                *(uint2*)(dst + AV_AHI + (row * STR_K + c4) * 2) = hh;
                *(uint2*)(dst + AV_ALO + (row * STR_K + c4) * 2) = ll;
            }
            #pragma unroll
            for (int i = 0; i < 2; i++) {
                int seg = tid + i * 256, row = seg >> 4, c4 = (seg & 15) << 2;
                uint2 hh, ll;
                cvt_hilo(lv[i], hh, ll);
                *(uint2*)(dst + AV_BHI + (row * STR_V + c4) * 2) = hh;
                *(uint2*)(dst + AV_BLO + (row * STR_V + c4) * 2) = ll;
            }
        }
        __syncthreads();
    }

    float* Ob = O + (size_t)b * Tt * EMBD + h * HEAD;
    const int rofs = lane >> 2, cofs = (lane & 3) * 2;
    #pragma unroll
    for (int mt = 0; mt < 2; mt++)
        #pragma unroll
        for (int nt = 0; nt < 4; nt++) {
            int m = m0 + wm * 32 + mt * 16 + rofs;
            int n = wn * 32 + nt * 8 + cofs;
            *(float2*)&Ob[(size_t)m * EMBD + n] =
                make_float2(acc[mt][nt][0], acc[mt][nt][1]);
            *(float2*)&Ob[(size_t)(m + 8) * EMBD + n] =
                make_float2(acc[mt][nt][2], acc[mt][nt][3]);
        }
}

// ===========================================================================
// Row softmax over 1024, fully-masked rows -> zeros (unchanged from R2).
// ===========================================================================
__global__ void __launch_bounds__(256)
softmax_kernel(float* __restrict__ Wt)
{
    __shared__ float red[8];
    float4* w = reinterpret_cast<float4*>(Wt + (size_t)blockIdx.x * Tt);
    const int t = threadIdx.x;
    float4 v = w[t];

    float m = fmaxf(fmaxf(v.x, v.y), fmaxf(v.z, v.w));
    #pragma unroll
    for (int o = 16; o > 0; o >>= 1) m = fmaxf(m, __shfl_xor_sync(0xffffffffu, m, o));
    if ((t & 31) == 0) red[t >> 5] = m;
    __syncthreads();
    float rm = red[0];
    #pragma unroll
    for (int i = 1; i < 8; i++) rm = fmaxf(rm, red[i]);

    const bool dead = (rm <= -1e29f);
    float e0 = dead ? 0.f : __expf(v.x - rm);
    float e1 = dead ? 0.f : __expf(v.y - rm);
    float e2 = dead ? 0.f : __expf(v.z - rm);
    float e3 = dead ? 0.f : __expf(v.w - rm);
    float s = e0 + e1 + e2 + e3;
    #pragma unroll
    for (int o = 16; o > 0; o >>= 1) s += __shfl_xor_sync(0xffffffffu, s, o);
    __syncthreads();
    if ((t & 31) == 0) red[t >> 5] = s;
    __syncthreads();
    float tot = 0.f;
    #pragma unroll
    for (int i = 0; i < 8; i++) tot += red[i];
    float inv = (tot > 0.f) ? (1.f / tot) : 0.f;

    w[t] = make_float4(e0 * inv, e1 * inv, e2 * inv, e3 * inv);
}

// ===========================================================================
extern "C" void kernel_launch(void* const* d_in, const int* in_sizes, int n_in,
                              void* d_out, int out_size)
{
    const float* x    = (const float*)d_in[0];
    const float* ctx  = (const float*)d_in[1];
    const int*   mask = (const int*)d_in[2];
    const float* WQ = (const float*)d_in[3];
    const float* WK = (const float*)d_in[4];
    const float* WV = (const float*)d_in[5];
    const float* WO = (const float*)d_in[6];
    float* out = (float*)d_out;

    float *qp, *kp, *vp, *op;
    cudaGetSymbolAddress((void**)&qp, g_Q);
    cudaGetSymbolAddress((void**)&kp, g_K);
    cudaGetSymbolAddress((void**)&vp, g_V);
    cudaGetSymbolAddress((void**)&op, g_O);

    const size_t merged_elems = (size_t)BTR * EMBD;
    const size_t weight_elems = (size_t)Bb * Hh * Tt * Tt;
    float* wt;
    if ((size_t)out_size >= merged_elems + weight_elems) {
        wt = out + merged_elems;
    } else {
        cudaGetSymbolAddress((void**)&wt, g_W);
    }

    const int SMEM_NT = 2 * STAGE_NT;   // 80 KB
    const int SMEM_AV = 2 * STAGE_AV;   // 58 KB
    cudaFuncSetAttribute(mma_nt<false>, cudaFuncAttributeMaxDynamicSharedMemorySize, SMEM_NT);
    cudaFuncSetAttribute(mma_nt<true>,  cudaFuncAttributeMaxDynamicSharedMemorySize, SMEM_NT);
    cudaFuncSetAttribute(mma_av, cudaFuncAttributeMaxDynamicSharedMemorySize, SMEM_AV);

    dim3 blk(256);
    dim3 gproj(EMBD / 128, BTR / 128, 1);   // (8, 32)

    mma_nt<false><<<gproj, blk, SMEM_NT>>>(x,   WQ, nullptr, qp, EMBD);
    mma_nt<false><<<gproj, blk, SMEM_NT>>>(ctx, WK, nullptr, kp, EMBD);
    mma_nt<false><<<gproj, blk, SMEM_NT>>>(ctx, WV, nullptr, vp, EMBD);

    dim3 gsc(Tt / 128, Tt / 128, Bb * Hh);  // (8, 8, 64)
    mma_nt<true><<<gsc, blk, SMEM_NT>>>(qp, kp, mask, wt, HEAD);

    softmax_kernel<<<Bb * Hh * Tt, 256>>>(wt);

    dim3 gav(1, Tt / 128, Bb * Hh);         // (1, 8, 64)
    mma_av<<<gav, blk, SMEM_AV>>>(wt, vp, op);

    mma_nt<false><<<gproj, blk, SMEM_NT>>>(op, WO, nullptr, out, EMBD);
}

// round 5
// speedup vs baseline: 2.3709x; 1.0425x over previous
#include <cuda_runtime.h>
#include <cuda_bf16.h>
#include <cstdint>

#define Bb   4
#define Tt   1024
#define EMBD 1024
#define Hh   16
#define HEAD 64
#define BTR  (Bb * Tt)
#define NEG_BIG (-1e30f)

static __device__ float g_Q[(size_t)BTR * EMBD];
static __device__ float g_K[(size_t)BTR * EMBD];
static __device__ float g_V[(size_t)BTR * EMBD];
static __device__ float g_O[(size_t)BTR * EMBD];

// ===========================================================================
// helpers
// ===========================================================================
__device__ __forceinline__ uint32_t smem_u32(const void* p) {
    uint32_t a;
    asm("{ .reg .u64 t; cvta.to.shared.u64 t, %1; cvt.u32.u64 %0, t; }" : "=r"(a) : "l"(p));
    return a;
}
__device__ __forceinline__ void ldsm4(uint32_t addr, uint32_t& r0, uint32_t& r1,
                                      uint32_t& r2, uint32_t& r3) {
    asm volatile("ldmatrix.sync.aligned.m8n8.x4.shared.b16 {%0,%1,%2,%3}, [%4];"
                 : "=r"(r0), "=r"(r1), "=r"(r2), "=r"(r3) : "r"(addr));
}
__device__ __forceinline__ void ldsm4t(uint32_t addr, uint32_t& r0, uint32_t& r1,
                                       uint32_t& r2, uint32_t& r3) {
    asm volatile("ldmatrix.sync.aligned.m8n8.x4.trans.shared.b16 {%0,%1,%2,%3}, [%4];"
                 : "=r"(r0), "=r"(r1), "=r"(r2), "=r"(r3) : "r"(addr));
}
__device__ __forceinline__ void mma_bf16(float (&d)[4], const uint32_t (&a)[4],
                                         uint32_t b0, uint32_t b1) {
    asm volatile("mma.sync.aligned.m16n8k16.row.col.f32.bf16.bf16.f32 "
                 "{%0,%1,%2,%3},{%4,%5,%6,%7},{%8,%9},{%0,%1,%2,%3};"
                 : "+f"(d[0]), "+f"(d[1]), "+f"(d[2]), "+f"(d[3])
                 : "r"(a[0]), "r"(a[1]), "r"(a[2]), "r"(a[3]), "r"(b0), "r"(b1));
}
__device__ __forceinline__ void cvt_hilo(float4 v, uint2& hi, uint2& lo) {
    __nv_bfloat162 h0 = __floats2bfloat162_rn(v.x, v.y);
    __nv_bfloat162 h1 = __floats2bfloat162_rn(v.z, v.w);
    float rx = v.x - __bfloat162float(h0.x);
    float ry = v.y - __bfloat162float(h0.y);
    float rz = v.z - __bfloat162float(h1.x);
    float rw = v.w - __bfloat162float(h1.y);
    __nv_bfloat162 l0 = __floats2bfloat162_rn(rx, ry);
    __nv_bfloat162 l1 = __floats2bfloat162_rn(rz, rw);
    hi = make_uint2(*(uint32_t*)&h0, *(uint32_t*)&h1);
    lo = make_uint2(*(uint32_t*)&l0, *(uint32_t*)&l1);
}
__device__ __forceinline__ void pack2(float x, float y, uint32_t& h, uint32_t& l) {
    __nv_bfloat162 hh = __floats2bfloat162_rn(x, y);
    float rx = x - __bfloat162float(hh.x);
    float ry = y - __bfloat162float(hh.y);
    __nv_bfloat162 ll = __floats2bfloat162_rn(rx, ry);
    h = *(uint32_t*)&hh;
    l = *(uint32_t*)&ll;
}

// ===========================================================================
// NT projection GEMM body (from R4, plain epilogue), K = 1024 fixed.
// 128x128 block, BK=32, 8 warps (2Mx4N), bf16 hi/lo 3-pass.
// ===========================================================================
#define STR_K  40
#define A_HI_O 0
#define A_LO_O 10240
#define B_HI_O 20480
#define B_LO_O 30720
#define STAGE_NT 40960

__device__ __forceinline__ void nt_body(const float* __restrict__ Ab,
                                        const float* __restrict__ Bp,
                                        float* __restrict__ Cb, char* sm)
{
    const int tid = threadIdx.x, lane = tid & 31, wid = tid >> 5;
    const int m0 = blockIdx.y * 128;
    const int n0 = blockIdx.x * 128;
    const int NC = EMBD / 32;

    float acc[4][4][4] = {};
    float4 la[4], lb[4];

    {
        #pragma unroll
        for (int i = 0; i < 4; i++) {
            int seg = tid + i * 256, row = seg >> 3, c4 = (seg & 7) << 2;
            la[i] = *(const float4*)&Ab[(size_t)(m0 + row) * EMBD + c4];
            lb[i] = *(const float4*)&Bp[(size_t)(n0 + row) * EMBD + c4];
        }
        #pragma unroll
        for (int i = 0; i < 4; i++) {
            int seg = tid + i * 256, row = seg >> 3, c4 = (seg & 7) << 2;
            uint2 h, l;
            cvt_hilo(la[i], h, l);
            *(uint2*)(sm + A_HI_O + (row * STR_K + c4) * 2) = h;
            *(uint2*)(sm + A_LO_O + (row * STR_K + c4) * 2) = l;
            cvt_hilo(lb[i], h, l);
            *(uint2*)(sm + B_HI_O + (row * STR_K + c4) * 2) = h;
            *(uint2*)(sm + B_LO_O + (row * STR_K + c4) * 2) = l;
        }
    }
    __syncthreads();

    const int wm = wid >> 2, wn = wid & 3;
    const int arow = lane & 15, acol8 = (lane >> 4) << 3;
    const int brow = (lane & 7) + ((lane >> 4) << 3), bcol8 = ((lane >> 3) & 1) << 3;
    const uint32_t sb0 = smem_u32(sm);

    for (int c = 0; c < NC; c++) {
        if (c + 1 < NC) {
            int k0n = (c + 1) * 32;
            #pragma unroll
            for (int i = 0; i < 4; i++) {
                int seg = tid + i * 256, row = seg >> 3, c4 = (seg & 7) << 2;
                la[i] = *(const float4*)&Ab[(size_t)(m0 + row) * EMBD + k0n + c4];
                lb[i] = *(const float4*)&Bp[(size_t)(n0 + row) * EMBD + k0n + c4];
            }
        }
        const uint32_t sbase = sb0 + (c & 1) * STAGE_NT;
        #pragma unroll
        for (int ks = 0; ks < 2; ks++) {
            const int k0 = ks * 16;
            uint32_t ah[4][4], al[4][4];
            #pragma unroll
            for (int mt = 0; mt < 4; mt++) {
                int r = wm * 64 + mt * 16 + arow;
                uint32_t ad = sbase + A_HI_O + (r * STR_K + k0 + acol8) * 2;
                ldsm4(ad, ah[mt][0], ah[mt][1], ah[mt][2], ah[mt][3]);
                ldsm4(ad + (A_LO_O - A_HI_O), al[mt][0], al[mt][1], al[mt][2], al[mt][3]);
            }
            uint32_t bh[4][2], bl[4][2];
            #pragma unroll
            for (int bt = 0; bt < 2; bt++) {
                int r = wn * 32 + bt * 16 + brow;
                uint32_t bd = sbase + B_HI_O + (r * STR_K + k0 + bcol8) * 2;
                ldsm4(bd, bh[2 * bt][0], bh[2 * bt][1], bh[2 * bt + 1][0], bh[2 * bt + 1][1]);
                ldsm4(bd + (B_LO_O - B_HI_O),
                      bl[2 * bt][0], bl[2 * bt][1], bl[2 * bt + 1][0], bl[2 * bt + 1][1]);
            }
            #pragma unroll
            for (int mt = 0; mt < 4; mt++)
                #pragma unroll
                for (int nt = 0; nt < 4; nt++) {
                    mma_bf16(acc[mt][nt], ah[mt], bh[nt][0], bh[nt][1]);
                    mma_bf16(acc[mt][nt], ah[mt], bl[nt][0], bl[nt][1]);
                    mma_bf16(acc[mt][nt], al[mt], bh[nt][0], bh[nt][1]);
                }
        }
        if (c + 1 < NC) {
            char* dst = sm + ((c + 1) & 1) * STAGE_NT;
            #pragma unroll
            for (int i = 0; i < 4; i++) {
                int seg = tid + i * 256, row = seg >> 3, c4 = (seg & 7) << 2;
                uint2 h, l;
                cvt_hilo(la[i], h, l);
                *(uint2*)(dst + A_HI_O + (row * STR_K + c4) * 2) = h;
                *(uint2*)(dst + A_LO_O + (row * STR_K + c4) * 2) = l;
                cvt_hilo(lb[i], h, l);
                *(uint2*)(dst + B_HI_O + (row * STR_K + c4) * 2) = h;
                *(uint2*)(dst + B_LO_O + (row * STR_K + c4) * 2) = l;
            }
        }
        __syncthreads();
    }

    const int rofs = lane >> 2, cofs = (lane & 3) * 2;
    #pragma unroll
    for (int mt = 0; mt < 4; mt++)
        #pragma unroll
        for (int nt = 0; nt < 4; nt++) {
            int m = m0 + wm * 64 + mt * 16 + rofs;
            int n = n0 + wn * 32 + nt * 8 + cofs;
            *(float2*)&Cb[(size_t)m * EMBD + n] =
                make_float2(acc[mt][nt][0], acc[mt][nt][1]);
            *(float2*)&Cb[(size_t)(m + 8) * EMBD + n] =
                make_float2(acc[mt][nt][2], acc[mt][nt][3]);
        }
}

__global__ void __launch_bounds__(256)
mma_qkv(const float* __restrict__ x, const float* __restrict__ ctx,
        const float* __restrict__ WQ, const float* __restrict__ WK,
        const float* __restrict__ WV,
        float* __restrict__ qp, float* __restrict__ kp, float* __restrict__ vp)
{
    extern __shared__ __align__(16) char sm[];
    const int z = blockIdx.z;
    const float* Ab = (z == 0) ? x : ctx;
    const float* Bp = (z == 0) ? WQ : ((z == 1) ? WK : WV);
    float* Cb = (z == 0) ? qp : ((z == 1) ? kp : vp);
    nt_body(Ab, Bp, Cb, sm);
}

__global__ void __launch_bounds__(256)
mma_out(const float* __restrict__ A, const float* __restrict__ W,
        float* __restrict__ C)
{
    extern __shared__ __align__(16) char sm[];
    nt_body(A, W, C, sm);
}

// ===========================================================================
// Fused attention: scores (bf16x3) + softmax + weights-write + AV.
// Grid (8 t-tiles, 64 z). 8 warps; warp tile 16 t-rows x 128 s-cols.
// Smem: Q tile + double-buffered K, V tiles; all 128x64, stride 72, hi/lo.
// ===========================================================================
#define QSTR  72
#define TILE_HL 36864          // hi (18432) + lo (18432)
#define F_LO  18432
#define FQ    0
#define FK0   36864
#define FK1   73728
#define FV0   110592
#define FV1   147456
#define FSMEM 184320

__device__ __forceinline__ void fill64(const float* __restrict__ src, char* dst, int tid) {
    #pragma unroll
    for (int i = 0; i < 8; i++) {
        int seg = tid + i * 256, row = seg >> 4, c4 = (seg & 15) << 2;
        float4 v = *(const float4*)&src[(size_t)row * EMBD + c4];
        uint2 h, l;
        cvt_hilo(v, h, l);
        uint32_t off = (uint32_t)(row * QSTR + c4) * 2;
        *(uint2*)(dst + off) = h;
        *(uint2*)(dst + F_LO + off) = l;
    }
}

// compute 16x128 score warp tile (bf16x3) from Q frags + K smem tile
#define SCORE_TILE(accv, smK)                                                    \
    do {                                                                          \
        _Pragma("unroll")                                                         \
        for (int ks = 0; ks < 4; ks++) {                                          \
            uint32_t bh[16][2], bl[16][2];                                        \
            _Pragma("unroll")                                                     \
            for (int bp = 0; bp < 8; bp++) {                                      \
                uint32_t bd = (smK) + ((bp * 16 + brow) * QSTR + ks * 16 + bcol8) * 2; \
                ldsm4(bd, bh[2 * bp][0], bh[2 * bp][1], bh[2 * bp + 1][0], bh[2 * bp + 1][1]); \
                ldsm4(bd + F_LO, bl[2 * bp][0], bl[2 * bp][1], bl[2 * bp + 1][0], bl[2 * bp + 1][1]); \
            }                                                                     \
            _Pragma("unroll")                                                     \
            for (int nt = 0; nt < 16; nt++) {                                     \
                mma_bf16(accv[nt], qh[ks], bh[nt][0], bh[nt][1]);                 \
                mma_bf16(accv[nt], qh[ks], bl[nt][0], bl[nt][1]);                 \
                mma_bf16(accv[nt], ql[ks], bh[nt][0], bh[nt][1]);                 \
            }                                                                     \
        }                                                                         \
    } while (0)

__global__ void __launch_bounds__(256)
fused_attn(const float* __restrict__ Q, const float* __restrict__ K,
           const float* __restrict__ V, const int* __restrict__ mask,
           float* __restrict__ Wt, float* __restrict__ O, int write_w)
{
    extern __shared__ __align__(16) char sm[];
    const uint32_t sb = smem_u32(sm);
    const int tid = threadIdx.x, lane = tid & 31, w = tid >> 5;
    const int z = blockIdx.y, b = z >> 4, h = z & 15;
    const int m0 = blockIdx.x * 128;

    const float* Qb = Q + (size_t)b * Tt * EMBD + h * HEAD;
    const float* Kb = K + (size_t)b * Tt * EMBD + h * HEAD;
    const float* Vb = V + (size_t)b * Tt * EMBD + h * HEAD;
    const int* mb = mask + (size_t)b * Tt * Tt + (size_t)m0 * Tt;

    const int g = lane >> 2, i2 = (lane & 3) << 1;
    const int arow = lane & 15, acol8 = (lane >> 4) << 3;
    const int brow = (lane & 7) + ((lane >> 4) << 3), bcol8 = ((lane >> 3) & 1) << 3;
    const int tbrow = (lane & 7) + (((lane >> 3) & 1) << 3), tbcol8 = (lane >> 4) << 3;

    // fill Q strip + K tile 0
    fill64(Qb + (size_t)m0 * EMBD, sm + FQ, tid);
    fill64(Kb, sm + FK0, tid);
    __syncthreads();

    // hoist Q fragments (persist across both phases)
    uint32_t qh[4][4], ql[4][4];
    #pragma unroll
    for (int ks = 0; ks < 4; ks++) {
        uint32_t ad = sb + FQ + ((w * 16 + arow) * QSTR + ks * 16 + acol8) * 2;
        ldsm4(ad, qh[ks][0], qh[ks][1], qh[ks][2], qh[ks][3]);
        ldsm4(ad + F_LO, ql[ks][0], ql[ks][1], ql[ks][2], ql[ks][3]);
    }

    const int trow = w * 16 + g;     // local row (0..127); +8 for second half

    // ---------------- phase 1: stats ----------------
    float rm0 = -3.0e38f, rm1 = -3.0e38f, rs0 = 0.f, rs1 = 0.f;
    for (int st = 0; st < 8; st++) {
        if (st < 7) fill64(Kb + (size_t)(st + 1) * 128 * EMBD,
                           sm + (((st + 1) & 1) ? FK1 : FK0), tid);
        float acc[16][4] = {};
        const uint32_t smK = sb + ((st & 1) ? FK1 : FK0);
        SCORE_TILE(acc, smK);

        // mask + scale
        const int* mr0 = mb + (size_t)trow * Tt + st * 128;
        const int* mr1 = mr0 + 8 * Tt;
        #pragma unroll
        for (int nt = 0; nt < 16; nt++) {
            int2 k0 = *(const int2*)&mr0[nt * 8 + i2];
            int2 k1 = *(const int2*)&mr1[nt * 8 + i2];
            acc[nt][0] = k0.x ? NEG_BIG : acc[nt][0] * 0.125f;
            acc[nt][1] = k0.y ? NEG_BIG : acc[nt][1] * 0.125f;
            acc[nt][2] = k1.x ? NEG_BIG : acc[nt][2] * 0.125f;
            acc[nt][3] = k1.y ? NEG_BIG : acc[nt][3] * 0.125f;
        }
        // tile max
        float t0 = -3.0e38f, t1 = -3.0e38f;
        #pragma unroll
        for (int nt = 0; nt < 16; nt++) {
            t0 = fmaxf(t0, fmaxf(acc[nt][0], acc[nt][1]));
            t1 = fmaxf(t1, fmaxf(acc[nt][2], acc[nt][3]));
        }
        t0 = fmaxf(t0, __shfl_xor_sync(0xffffffffu, t0, 1));
        t0 = fmaxf(t0, __shfl_xor_sync(0xffffffffu, t0, 2));
        t1 = fmaxf(t1, __shfl_xor_sync(0xffffffffu, t1, 1));
        t1 = fmaxf(t1, __shfl_xor_sync(0xffffffffu, t1, 2));
        float nm0 = fmaxf(rm0, t0), nm1 = fmaxf(rm1, t1);
        float s0 = 0.f, s1 = 0.f;
        #pragma unroll
        for (int nt = 0; nt < 16; nt++) {
            s0 += __expf(acc[nt][0] - nm0) + __expf(acc[nt][1] - nm0);
            s1 += __expf(acc[nt][2] - nm1) + __expf(acc[nt][3] - nm1);
        }
        s0 += __shfl_xor_sync(0xffffffffu, s0, 1);
        s0 += __shfl_xor_sync(0xffffffffu, s0, 2);
        s1 += __shfl_xor_sync(0xffffffffu, s1, 1);
        s1 += __shfl_xor_sync(0xffffffffu, s1, 2);
        rs0 = rs0 * __expf(rm0 - nm0) + s0;  rm0 = nm0;
        rs1 = rs1 * __expf(rm1 - nm1) + s1;  rm1 = nm1;
        __syncthreads();
    }
    const float inv0 = (rm0 <= -1e29f) ? 0.f : 1.f / rs0;
    const float inv1 = (rm1 <= -1e29f) ? 0.f : 1.f / rs1;

    // ---------------- phase 2: weights + AV ----------------
    fill64(Kb, sm + FK0, tid);
    fill64(Vb, sm + FV0, tid);
    __syncthreads();

    float acco[8][4] = {};
    float* wrow0 = Wt + (size_t)z * Tt * Tt + (size_t)(m0 + trow) * Tt;
    float* wrow1 = wrow0 + 8 * Tt;

    for (int st = 0; st < 8; st++) {
        if (st < 7) {
            const int nb = (st + 1) & 1;
            fill64(Kb + (size_t)(st + 1) * 128 * EMBD, sm + (nb ? FK1 : FK0), tid);
            fill64(Vb + (size_t)(st + 1) * 128 * EMBD, sm + (nb ? FV1 : FV0), tid);
        }
        float acc[16][4] = {};
        const uint32_t smK = sb + ((st & 1) ? FK1 : FK0);
        const uint32_t smV = sb + ((st & 1) ? FV1 : FV0);
        SCORE_TILE(acc, smK);

        const int* mr0 = mb + (size_t)trow * Tt + st * 128;
        const int* mr1 = mr0 + 8 * Tt;
        #pragma unroll
        for (int nt = 0; nt < 16; nt++) {
            int2 k0 = *(const int2*)&mr0[nt * 8 + i2];
            int2 k1 = *(const int2*)&mr1[nt * 8 + i2];
            float v0 = k0.x ? NEG_BIG : acc[nt][0] * 0.125f;
            float v1 = k0.y ? NEG_BIG : acc[nt][1] * 0.125f;
            float v2 = k1.x ? NEG_BIG : acc[nt][2] * 0.125f;
            float v3 = k1.y ? NEG_BIG : acc[nt][3] * 0.125f;
            acc[nt][0] = __expf(v0 - rm0) * inv0;
            acc[nt][1] = __expf(v1 - rm0) * inv0;
            acc[nt][2] = __expf(v2 - rm1) * inv1;
            acc[nt][3] = __expf(v3 - rm1) * inv1;
        }
        if (write_w) {
            #pragma unroll
            for (int nt = 0; nt < 16; nt++) {
                *(float2*)&wrow0[st * 128 + nt * 8 + i2] = make_float2(acc[nt][0], acc[nt][1]);
                *(float2*)&wrow1[st * 128 + nt * 8 + i2] = make_float2(acc[nt][2], acc[nt][3]);
            }
        }
        // AV: p (registers) x V (smem)
        #pragma unroll
        for (int j = 0; j < 8; j++) {
            uint32_t ph[4], pl[4];
            pack2(acc[2 * j][0],     acc[2 * j][1],     ph[0], pl[0]);
            pack2(acc[2 * j][2],     acc[2 * j][3],     ph[1], pl[1]);
            pack2(acc[2 * j + 1][0], acc[2 * j + 1][1], ph[2], pl[2]);
            pack2(acc[2 * j + 1][2], acc[2 * j + 1][3], ph[3], pl[3]);
            uint32_t vh[8][2], vl[8][2];
            #pragma unroll
            for (int bt = 0; bt < 4; bt++) {
                uint32_t vd = smV + ((j * 16 + tbrow) * QSTR + bt * 16 + tbcol8) * 2;
                ldsm4t(vd, vh[2 * bt][0], vh[2 * bt][1], vh[2 * bt + 1][0], vh[2 * bt + 1][1]);
                ldsm4t(vd + F_LO, vl[2 * bt][0], vl[2 * bt][1], vl[2 * bt + 1][0], vl[2 * bt + 1][1]);
            }
            #pragma unroll
            for (int ntv = 0; ntv < 8; ntv++) {
                mma_bf16(acco[ntv], ph, vh[ntv][0], vh[ntv][1]);
                mma_bf16(acco[ntv], ph, vl[ntv][0], vl[ntv][1]);
                mma_bf16(acco[ntv], pl, vh[ntv][0], vh[ntv][1]);
            }
        }
        __syncthreads();
    }

    // write O (merged [B,T,EMB] layout)
    float* Ob = O + (size_t)b * Tt * EMBD + h * HEAD + (size_t)(m0 + trow) * EMBD;
    #pragma unroll
    for (int ntv = 0; ntv < 8; ntv++) {
        *(float2*)&Ob[ntv * 8 + i2] = make_float2(acco[ntv][0], acco[ntv][1]);
        *(float2*)&Ob[8 * EMBD + ntv * 8 + i2] = make_float2(acco[ntv][2], acco[ntv][3]);
    }
}

// ===========================================================================
extern "C" void kernel_launch(void* const* d_in, const int* in_sizes, int n_in,
                              void* d_out, int out_size)
{
    const float* x    = (const float*)d_in[0];
    const float* ctx  = (const float*)d_in[1];
    const int*   mask = (const int*)d_in[2];
    const float* WQ = (const float*)d_in[3];
    const float* WK = (const float*)d_in[4];
    const float* WV = (const float*)d_in[5];
    const float* WO = (const float*)d_in[6];
    float* out = (float*)d_out;

    float *qp, *kp, *vp, *op;
    cudaGetSymbolAddress((void**)&qp, g_Q);
    cudaGetSymbolAddress((void**)&kp, g_K);
    cudaGetSymbolAddress((void**)&vp, g_V);
    cudaGetSymbolAddress((void**)&op, g_O);

    const size_t merged_elems = (size_t)BTR * EMBD;
    const size_t weight_elems = (size_t)Bb * Hh * Tt * Tt;
    const int write_w = ((size_t)out_size >= merged_elems + weight_elems) ? 1 : 0;
    float* wt = write_w ? (out + merged_elems) : op;  // dummy target if unused

    const int SMEM_NT = 2 * STAGE_NT;   // 80 KB
    cudaFuncSetAttribute(mma_qkv, cudaFuncAttributeMaxDynamicSharedMemorySize, SMEM_NT);
    cudaFuncSetAttribute(mma_out, cudaFuncAttributeMaxDynamicSharedMemorySize, SMEM_NT);
    cudaFuncSetAttribute(fused_attn, cudaFuncAttributeMaxDynamicSharedMemorySize, FSMEM);

    dim3 blk(256);

    // Q/K/V projections, one launch
    dim3 gqkv(EMBD / 128, BTR / 128, 3);
    mma_qkv<<<gqkv, blk, SMEM_NT>>>(x, ctx, WQ, WK, WV, qp, kp, vp);

    // fused scores+softmax+weights+AV
    dim3 gf(Tt / 128, Bb * Hh);
    fused_attn<<<gf, blk, FSMEM>>>(qp, kp, vp, mask, wt, op, write_w);

    // output projection
    dim3 gout(EMBD / 128, BTR / 128);
    mma_out<<<gout, blk, SMEM_NT>>>(op, WO, out);
}